// round 12
// baseline (speedup 1.0000x reference)
#include <cuda_runtime.h>
#include <cuda_fp16.h>
#include <cstdint>
#include <math.h>

#define BATCH 16
#define SEQ   512
#define MTOT  8192          // m = s*16 + b
#define NXG   4096
#define KD    1024

// ---------------- device scratch ----------------
__device__ float  g_X0T[(size_t)KD * MTOT];   // [k][m] (tf32-rounded)
__device__ float  g_YT [(size_t)KD * MTOT];   // [k][m] (rounded)
__device__ float  g_A1T[(size_t)KD * MTOT];   // [k][m] (rounded)
__device__ float  g_A2 [(size_t)MTOT * KD];   // [m][n]
__device__ float  g_XG [(size_t)MTOT * NXG];  // [s][n(4096)][b(16)]
__device__ float  g_Wr [(size_t)NXG * KD];    // rounded weights (current GEMM)
__device__ float  g_bXG[NXG];
// blocked h: [parity][dir][blk(16)][b(16)][u(32)] halves; 1KB contiguous per CTA
__device__ __align__(256) __half g_h16[2][2][16][BATCH][32];
__device__ unsigned g_tag[2][64][32];         // per-CTA barrier slots, 128B padded

// ---------------- helpers ----------------
__device__ __forceinline__ unsigned f2tf(float x) {
    unsigned r;
    asm("cvt.rna.tf32.f32 %0, %1;" : "=r"(r) : "f"(x));
    return r;
}
__device__ __forceinline__ float tfr(float x) { return __uint_as_float(f2tf(x)); }

__device__ __forceinline__ void mma_tf32(float& c0, float& c1, float& c2, float& c3,
                                         unsigned a0, unsigned a1, unsigned a2, unsigned a3,
                                         unsigned b0, unsigned b1) {
    asm volatile(
        "mma.sync.aligned.m16n8k8.row.col.f32.tf32.tf32.f32 "
        "{%0,%1,%2,%3},{%4,%5,%6,%7},{%8,%9},{%0,%1,%2,%3};"
        : "+f"(c0), "+f"(c1), "+f"(c2), "+f"(c3)
        : "r"(a0), "r"(a1), "r"(a2), "r"(a3), "r"(b0), "r"(b1));
}
__device__ __forceinline__ void mma_f16(float& c0, float& c1, float& c2, float& c3,
                                        unsigned a0, unsigned a1, unsigned a2, unsigned a3,
                                        unsigned b0, unsigned b1) {
    asm volatile(
        "mma.sync.aligned.m16n8k16.row.col.f32.f16.f16.f32 "
        "{%0,%1,%2,%3},{%4,%5,%6,%7},{%8,%9},{%0,%1,%2,%3};"
        : "+f"(c0), "+f"(c1), "+f"(c2), "+f"(c3)
        : "r"(a0), "r"(a1), "r"(a2), "r"(a3), "r"(b0), "r"(b1));
}
__device__ __forceinline__ void cp16(void* smem, const void* gmem) {
    unsigned s = (unsigned)__cvta_generic_to_shared(smem);
    asm volatile("cp.async.ca.shared.global [%0], [%1], 16;" :: "r"(s), "l"(gmem));
}
__device__ __forceinline__ void cp16cg(void* smem, const void* gmem) {
    unsigned s = (unsigned)__cvta_generic_to_shared(smem);
    asm volatile("cp.async.cg.shared.global [%0], [%1], 16;" :: "r"(s), "l"(gmem));
}
__device__ __forceinline__ void cp_commit() { asm volatile("cp.async.commit_group;"); }
__device__ __forceinline__ void cp_wait1()  { asm volatile("cp.async.wait_group 1;"); }
__device__ __forceinline__ void cp_wait0()  { asm volatile("cp.async.wait_group 0;"); }
__device__ __forceinline__ float sigm(float x) { return 1.0f / (1.0f + __expf(-x)); }
__device__ __forceinline__ unsigned packh2(float a, float b) {
    __half2 h = __floats2half2_rn(a, b);
    return *(unsigned*)&h;
}

// ---------------- k_roundbias: round W into g_Wr (+ bias + tag reset) ----------
__global__ void k_roundbias(const float* __restrict__ src, int n4,
                            const float* __restrict__ bi, const float* __restrict__ bh,
                            int aux) {
    int gid = blockIdx.x * blockDim.x + threadIdx.x;
    if (gid < n4) {
        float4 v = ((const float4*)src)[gid];
        v.x = tfr(v.x); v.y = tfr(v.y); v.z = tfr(v.z); v.w = tfr(v.w);
        ((float4*)g_Wr)[gid] = v;
    } else if (aux) {
        int r = gid - n4;
        if (r < NXG) {
            g_bXG[r] = bi[r] + bh[r];
        } else if (r < NXG + 128) {
            int r2 = r - NXG;
            g_tag[r2 >> 6][r2 & 63][0] = 0u;
        }
    }
}

// ---------------- k_embed: X0T[k][s*16+b] rounded (R4) ----------------
__global__ void k_embed(const int* __restrict__ x, const float* __restrict__ lang,
                        const float* __restrict__ emb) {
    __shared__ int toks[BATCH];
    int s = blockIdx.x;
    int tid = threadIdx.x;                      // 256
    if (tid < BATCH) toks[tid] = x[tid * SEQ + s];
    __syncthreads();
    int k = tid * 4;
    float4 v[BATCH];
    if (k < 768) {
        #pragma unroll
        for (int b = 0; b < BATCH; b++)
            v[b] = *(const float4*)(lang + ((size_t)(b * SEQ + s)) * 768 + k);
    } else {
        #pragma unroll
        for (int b = 0; b < BATCH; b++)
            v[b] = *(const float4*)(emb + (size_t)toks[b] * 256 + (k - 768));
    }
    #pragma unroll
    for (int i = 0; i < 4; i++) {
        float* dst = g_X0T + (size_t)(k + i) * MTOT + s * 16;
        #pragma unroll
        for (int bq = 0; bq < 4; bq++) {
            float4 w;
            w.x = tfr(((float*)&v[bq * 4 + 0])[i]);
            w.y = tfr(((float*)&v[bq * 4 + 1])[i]);
            w.z = tfr(((float*)&v[bq * 4 + 2])[i]);
            w.w = tfr(((float*)&v[bq * 4 + 3])[i]);
            *(float4*)(dst + bq * 4) = w;
        }
    }
}

// ---------------- tf32 GEMM (R4 config — best measured) ----------------
#define AST 136
#define BST 20
#define GSMEM 58368

__global__ __launch_bounds__(256, 1)
void k_gemm(int asel, int csel, const float* __restrict__ bias_ext,
            int N, int act, int mode, int rnd) {
    extern __shared__ float sg[];
    float* As0 = sg;
    float* As1 = sg + 2176;
    float* Bs0 = sg + 4352;
    float* Bs1 = sg + 9472;

    const float* A = (asel == 0) ? g_X0T : (asel == 1 ? g_YT : g_A1T);
    const float* bias = bias_ext ? bias_ext : g_bXG;

    int m0 = blockIdx.y * 128;
    int n0 = blockIdx.x * 256;
    int tid = threadIdx.x, lane = tid & 31, warp = tid >> 5;
    int wm = (warp >> 2) * 64;
    int wn = (warp & 3) * 64;

    float acc[4][8][4];
    #pragma unroll
    for (int a = 0; a < 4; a++)
        #pragma unroll
        for (int b = 0; b < 8; b++)
            #pragma unroll
            for (int q = 0; q < 4; q++) acc[a][b][q] = 0.f;

    auto load_slice = [&](int kk, int buf) {
        int k0 = kk * 16;
        float* Ad = buf ? As1 : As0;
        float* Bd = buf ? Bs1 : Bs0;
        #pragma unroll
        for (int j = 0; j < 2; j++) {
            int id = tid + j * 256;
            int kr = id >> 5, mc = (id & 31) * 4;
            cp16(&Ad[kr * AST + mc], A + (size_t)(k0 + kr) * MTOT + m0 + mc);
        }
        #pragma unroll
        for (int j = 0; j < 4; j++) {
            int id = tid + j * 256;
            int row = id >> 2, kc = (id & 3) * 4;
            cp16(&Bd[row * BST + kc], g_Wr + (size_t)(n0 + row) * KD + k0 + kc);
        }
        cp_commit();
    };

    load_slice(0, 0);

    #pragma unroll 1
    for (int kk = 0; kk < 64; kk++) {
        int buf = kk & 1;
        if (kk < 63) load_slice(kk + 1, buf ^ 1);
        if (kk < 63) cp_wait1(); else cp_wait0();
        __syncthreads();
        const float* Ab = buf ? As1 : As0;
        const float* Bb = buf ? Bs1 : Bs0;

        #pragma unroll
        for (int kt = 0; kt < 2; kt++) {
            int kc = kt * 8 + (lane & 3);
            unsigned af[4][4];
            #pragma unroll
            for (int mt = 0; mt < 4; mt++) {
                int m = wm + mt * 16 + (lane >> 2);
                af[mt][0] = __float_as_uint(Ab[kc * AST + m]);
                af[mt][1] = __float_as_uint(Ab[kc * AST + m + 8]);
                af[mt][2] = __float_as_uint(Ab[(kc + 4) * AST + m]);
                af[mt][3] = __float_as_uint(Ab[(kc + 4) * AST + m + 8]);
            }
            #pragma unroll
            for (int nt = 0; nt < 8; nt++) {
                int rn = wn + nt * 8 + (lane >> 2);
                unsigned b0 = __float_as_uint(Bb[rn * BST + kc]);
                unsigned b1 = __float_as_uint(Bb[rn * BST + kc + 4]);
                #pragma unroll
                for (int mt = 0; mt < 4; mt++)
                    mma_tf32(acc[mt][nt][0], acc[mt][nt][1], acc[mt][nt][2], acc[mt][nt][3],
                             af[mt][0], af[mt][1], af[mt][2], af[mt][3], b0, b1);
            }
        }
        __syncthreads();
    }

    float* C = (csel == 2) ? g_A1T : (csel == 3 ? g_A2 : g_XG);
    #pragma unroll
    for (int mt = 0; mt < 4; mt++) {
        #pragma unroll
        for (int nt = 0; nt < 8; nt++) {
            int r = m0 + wm + mt * 16 + (lane >> 2);
            int n = n0 + wn + nt * 8 + 2 * (lane & 3);
            float v0 = acc[mt][nt][0] + bias[n];
            float v1 = acc[mt][nt][1] + bias[n + 1];
            float v2 = acc[mt][nt][2] + bias[n];
            float v3 = acc[mt][nt][3] + bias[n + 1];
            if (act) {
                v0 = v0 > 0.f ? v0 : 0.01f * v0;
                v1 = v1 > 0.f ? v1 : 0.01f * v1;
                v2 = v2 > 0.f ? v2 : 0.01f * v2;
                v3 = v3 > 0.f ? v3 : 0.01f * v3;
            }
            if (rnd) { v0 = tfr(v0); v1 = tfr(v1); v2 = tfr(v2); v3 = tfr(v3); }
            if (mode == 1) {
                int s1 = r >> 4, b1v = r & 15;
                int s2 = (r + 8) >> 4, b2v = (r + 8) & 15;
                C[((size_t)s1 * NXG + n) * 16 + b1v]     = v0;
                C[((size_t)s1 * NXG + n + 1) * 16 + b1v] = v1;
                C[((size_t)s2 * NXG + n) * 16 + b2v]     = v2;
                C[((size_t)s2 * NXG + n + 1) * 16 + b2v] = v3;
            } else if (mode == 2) {
                C[(size_t)n * MTOT + r]           = v0;
                C[(size_t)(n + 1) * MTOT + r]     = v1;
                C[(size_t)n * MTOT + r + 8]       = v2;
                C[(size_t)(n + 1) * MTOT + r + 8] = v3;
            } else {
                *(float2*)(C + (size_t)r * N + n)       = make_float2(v0, v1);
                *(float2*)(C + (size_t)(r + 8) * N + n) = make_float2(v2, v3);
            }
        }
    }
}

// ---------------- persistent bidirectional LSTM recurrence ----------------
// 32 CTAs x 512 threads. CTA c: dir = c>>4, blk = c&15, units u0c = blk*32.
// Warp w (16 warps): gate g = w&3, k-quarter q = w>>2.
// Only 16 producers per direction -> 16-slot poll, small tail.
#define HSTR 520
#define PSTR 18
#define RSMEM 57344   // hsm 16640 + part 36864 + hout 1280 + yout 2560

__global__ __launch_bounds__(512, 1)
void k_rec(const float* __restrict__ Whh, const int* __restrict__ lengths) {
    extern __shared__ char smraw[];
    __half* hsm  = (__half*)smraw;                       // [16][520] halves
    float*  part = (float*)(smraw + 16640);              // [4][4][32][18]
    __half* hout = (__half*)(smraw + 16640 + 36864);     // [16][40] halves
    float*  yout = (float*)(smraw + 16640 + 36864 + 1280); // [32][20] floats

    int tid = threadIdx.x, lane = tid & 31, w = tid >> 5;
    int dir = blockIdx.x >> 4;
    int blk = blockIdx.x & 15;
    int u0c = blk * 32;
    int g = w & 3, q = w >> 2;

    // persistent fp16 weights: warp (g,q): 4 n-tiles x 8 k16-tiles x 2 regs = 64
    unsigned wB[4][8][2];
    #pragma unroll
    for (int nt = 0; nt < 4; nt++) {
        const float* wr = Whh + ((size_t)(dir * 2048 + g * 512 + u0c + nt * 8 + (lane >> 2))) * 512;
        #pragma unroll
        for (int kt = 0; kt < 8; kt++) {
            int kb = q * 128 + kt * 16 + (lane & 3) * 2;
            wB[nt][kt][0] = packh2(wr[kb],     wr[kb + 1]);
            wB[nt][kt][1] = packh2(wr[kb + 8], wr[kb + 9]);
        }
    }

    int b_up = tid & 15, u_up = tid >> 4;     // cell ownership: 16b x 32u
    int len = lengths[b_up];
    float hreg = 0.f, creg = 0.f;
    unsigned* myslot = &g_tag[dir][blk][0];
    const unsigned* pollslot = &g_tag[dir][lane & 15][0];

    // xg prefetch (step 0)
    float xgn[4];
    {
        int s0 = dir ? (SEQ - 1) : 0;
        #pragma unroll
        for (int gg = 0; gg < 4; gg++)
            xgn[gg] = __ldcg(&g_XG[((size_t)s0 * NXG + dir * 2048 + gg * 512 + u0c + u_up) * 16 + b_up]);
    }

    #pragma unroll 1
    for (int t = 0; t < SEQ; t++) {
        int s = dir ? (SEQ - 1 - t) : t;

        float xgv[4];
        #pragma unroll
        for (int gg = 0; gg < 4; gg++) xgv[gg] = xgn[gg];
        if (t < SEQ - 1) {
            int s1 = dir ? (SEQ - 2 - t) : (t + 1);
            #pragma unroll
            for (int gg = 0; gg < 4; gg++)
                xgn[gg] = __ldcg(&g_XG[((size_t)s1 * NXG + dir * 2048 + gg * 512 + u0c + u_up) * 16 + b_up]);
        }

        float acc[4][4];
        #pragma unroll
        for (int nt = 0; nt < 4; nt++)
            #pragma unroll
            for (int c = 0; c < 4; c++) acc[nt][c] = 0.f;

        if (t > 0) {
            // poll the 16 producers of this direction (warp 1, lanes 0-15)
            if (w == 1 && lane < 16) {
                unsigned v;
                do {
                    asm volatile("ld.acquire.gpu.global.u32 %0, [%1];" : "=r"(v) : "l"(pollslot));
                } while (v < (unsigned)t);
            }
            __syncthreads();

            // stage h(t-1): 16KB fully coalesced (blocked [blk][b][u] layout)
            const __half* src = &g_h16[(t + 1) & 1][dir][0][0][0];
            #pragma unroll
            for (int j = 0; j < 2; j++) {
                int ch = tid + j * 512;               // 0..1023 chunks of 8 halves
                int blk2 = ch >> 6, bb = (ch >> 2) & 15, u8 = ch & 3;
                cp16cg(&hsm[bb * HSTR + blk2 * 32 + u8 * 8], src + ch * 8);
            }
            cp_commit();
            cp_wait0();
            __syncthreads();

            int b0r = lane >> 2;
            #pragma unroll
            for (int kt = 0; kt < 8; kt++) {
                int kb = q * 128 + kt * 16 + (lane & 3) * 2;
                unsigned a0 = *(const unsigned*)&hsm[b0r * HSTR + kb];
                unsigned a1 = *(const unsigned*)&hsm[(b0r + 8) * HSTR + kb];
                unsigned a2 = *(const unsigned*)&hsm[b0r * HSTR + kb + 8];
                unsigned a3 = *(const unsigned*)&hsm[(b0r + 8) * HSTR + kb + 8];
                #pragma unroll
                for (int nt = 0; nt < 4; nt++)
                    mma_f16(acc[nt][0], acc[nt][1], acc[nt][2], acc[nt][3],
                            a0, a1, a2, a3, wB[nt][kt][0], wB[nt][kt][1]);
            }
        }

        // write partials: part[q][g][u(32)][b(18 pad)]
        #pragma unroll
        for (int nt = 0; nt < 4; nt++) {
            int uu = nt * 8 + 2 * (lane & 3);
            int rr = lane >> 2;
            float* pb = part + ((q * 4 + g) * 32) * PSTR;
            pb[uu * PSTR + rr]           = acc[nt][0];
            pb[(uu + 1) * PSTR + rr]     = acc[nt][1];
            pb[uu * PSTR + rr + 8]       = acc[nt][2];
            pb[(uu + 1) * PSTR + rr + 8] = acc[nt][3];
        }
        __syncthreads();

        // cell update: all 512 threads, one (b,u) each
        {
            float v[4];
            #pragma unroll
            for (int gg = 0; gg < 4; gg++) {
                v[gg] = xgv[gg];
                #pragma unroll
                for (int qq = 0; qq < 4; qq++)
                    v[gg] += part[((qq * 4 + gg) * 32 + u_up) * PSTR + b_up];
            }
            float gi = sigm(v[0]);
            float gf = sigm(v[1]);
            float gg2 = tanhf(v[2]);
            float go = sigm(v[3]);
            float cn = gf * creg + gi * gg2;
            float hn = go * tanhf(cn);
            bool active = s < len;
            float y = active ? hn : 0.f;
            if (active) { creg = cn; hreg = hn; }
            hout[b_up * 40 + u_up] = __float2half_rn(hreg);
            yout[u_up * 20 + b_up] = tfr(y);
        }
        __syncthreads();

        if (w == 0) {
            // h publish: 1KB contiguous, then release
            __half* dst = &g_h16[t & 1][dir][blk][0][0];
            #pragma unroll
            for (int it = 0; it < 2; it++) {
                int ch = lane + it * 32;              // 0..63 chunks of 8 halves
                int bb = ch >> 2, u8 = ch & 3;
                *(float4*)&dst[ch * 8] = *(const float4*)&hout[bb * 40 + u8 * 8];
            }
            __syncwarp();
            if (lane == 0)
                asm volatile("st.release.gpu.global.u32 [%0], %1;"
                             :: "l"(myslot), "r"((unsigned)(t + 1)));
        } else if (w == 2) {
            // y publish (transposed [k][m], tf32-rounded): 32u x 64B, off-chain
            #pragma unroll
            for (int it = 0; it < 4; it++) {
                int ch = lane + it * 32;              // 0..127 chunks of 16B
                int uu = ch >> 2, b4 = (ch & 3) * 4;
                *(float4*)&g_YT[(size_t)(dir * 512 + u0c + uu) * MTOT + s * 16 + b4] =
                    *(const float4*)&yout[uu * 20 + b4];
            }
        }
    }
}

// ---------------- head ----------------
__global__ void k_head(const float* __restrict__ W3, const float* __restrict__ b3,
                       float* __restrict__ out) {
    int gw = (blockIdx.x * blockDim.x + threadIdx.x) >> 5;
    int lane = threadIdx.x & 31;
    if (gw >= MTOT) return;
    const float* a = g_A2 + (size_t)gw * KD;
    float s0 = 0, s1 = 0, s2 = 0, s3 = 0, s4 = 0;
    for (int k = lane; k < KD; k += 32) {
        float v = a[k];
        s0 += v * W3[k];
        s1 += v * W3[1024 + k];
        s2 += v * W3[2048 + k];
        s3 += v * W3[3072 + k];
        s4 += v * W3[4096 + k];
    }
    #pragma unroll
    for (int o = 16; o; o >>= 1) {
        s0 += __shfl_down_sync(0xffffffffu, s0, o);
        s1 += __shfl_down_sync(0xffffffffu, s1, o);
        s2 += __shfl_down_sync(0xffffffffu, s2, o);
        s3 += __shfl_down_sync(0xffffffffu, s3, o);
        s4 += __shfl_down_sync(0xffffffffu, s4, o);
    }
    if (lane == 0) {
        int b = gw & 15, s = gw >> 4;
        float* o = out + ((size_t)b * SEQ + s) * 5;
        o[0] = s0 + b3[0];
        o[1] = s1 + b3[1];
        o[2] = s2 + b3[2];
        o[3] = s3 + b3[3];
        o[4] = s4 + b3[4];
    }
}

// ---------------- launch ----------------
extern "C" void kernel_launch(void* const* d_in, const int* in_sizes, int n_in,
                              void* d_out, int out_size) {
    const int*   x    = (const int*)d_in[0];
    const int*   len  = (const int*)d_in[1];
    const float* lang = (const float*)d_in[2];
    const float* emb  = (const float*)d_in[3];
    const float* W_ih = (const float*)d_in[4];
    const float* W_hh = (const float*)d_in[5];
    const float* b_ih = (const float*)d_in[6];
    const float* b_hh = (const float*)d_in[7];
    const float* W1   = (const float*)d_in[8];
    const float* b1   = (const float*)d_in[9];
    const float* W2   = (const float*)d_in[10];
    const float* b2   = (const float*)d_in[11];
    const float* W3   = (const float*)d_in[12];
    const float* b3   = (const float*)d_in[13];
    float* out = (float*)d_out;

    cudaFuncSetAttribute(k_gemm, cudaFuncAttributeMaxDynamicSharedMemorySize, GSMEM);
    cudaFuncSetAttribute(k_rec,  cudaFuncAttributeMaxDynamicSharedMemorySize, RSMEM);

    k_embed<<<SEQ, 256>>>(x, lang, emb);

    for (int l = 0; l < 2; l++) {
        k_roundbias<<<4113, 256>>>(W_ih + (size_t)l * NXG * KD, NXG * KD / 4,
                                   b_ih + (size_t)l * NXG, b_hh + (size_t)l * NXG, 1);
        k_gemm<<<dim3(NXG / 256, MTOT / 128), 256, GSMEM>>>(
            l == 0 ? 0 : 1, 4, nullptr, NXG, 0, 1, 0);
        k_rec<<<32, 512, RSMEM>>>(W_hh + (size_t)l * 2 * 2048 * 512, len);
    }

    k_roundbias<<<1024, 256>>>(W1, KD * KD / 4, nullptr, nullptr, 0);
    k_gemm<<<dim3(KD / 256, MTOT / 128), 256, GSMEM>>>(1, 2, b1, KD, 1, 2, 1);
    k_roundbias<<<1024, 256>>>(W2, KD * KD / 4, nullptr, nullptr, 0);
    k_gemm<<<dim3(KD / 256, MTOT / 128), 256, GSMEM>>>(2, 3, b2, KD, 1, 0, 0);
    k_head<<<MTOT / 8, 256>>>(W3, b3, out);
}

// round 13
// speedup vs baseline: 1.5135x; 1.5135x over previous
#include <cuda_runtime.h>
#include <cuda_fp16.h>
#include <cstdint>
#include <math.h>

#define BATCH 16
#define SEQ   512
#define MTOT  8192          // m = s*16 + b
#define NXG   4096
#define KD    1024

// ---------------- device scratch ----------------
__device__ float  g_X0T[(size_t)KD * MTOT];   // [k][m] (tf32-rounded)
__device__ float  g_YT [(size_t)KD * MTOT];   // [k][m] (rounded)
__device__ float  g_A1T[(size_t)KD * MTOT];   // [k][m] (rounded)
__device__ float  g_A2 [(size_t)MTOT * KD];   // [m][n]
__device__ float  g_XG [(size_t)MTOT * NXG];  // [s][n(4096)][b(16)]
__device__ float  g_Wr [(size_t)NXG * KD];    // rounded weights (current GEMM)
__device__ float  g_bXG[NXG];
__device__ __half g_h16[2][2][BATCH][512];    // [parity][dir][b][k] fp16
__device__ unsigned g_tag[2][64][32];         // per-CTA barrier slots, 128B padded

// ---------------- helpers ----------------
__device__ __forceinline__ unsigned f2tf(float x) {
    unsigned r;
    asm("cvt.rna.tf32.f32 %0, %1;" : "=r"(r) : "f"(x));
    return r;
}
__device__ __forceinline__ float tfr(float x) { return __uint_as_float(f2tf(x)); }

__device__ __forceinline__ void mma_tf32(float& c0, float& c1, float& c2, float& c3,
                                         unsigned a0, unsigned a1, unsigned a2, unsigned a3,
                                         unsigned b0, unsigned b1) {
    asm volatile(
        "mma.sync.aligned.m16n8k8.row.col.f32.tf32.tf32.f32 "
        "{%0,%1,%2,%3},{%4,%5,%6,%7},{%8,%9},{%0,%1,%2,%3};"
        : "+f"(c0), "+f"(c1), "+f"(c2), "+f"(c3)
        : "r"(a0), "r"(a1), "r"(a2), "r"(a3), "r"(b0), "r"(b1));
}
__device__ __forceinline__ void mma_f16(float& c0, float& c1, float& c2, float& c3,
                                        unsigned a0, unsigned a1, unsigned a2, unsigned a3,
                                        unsigned b0, unsigned b1) {
    asm volatile(
        "mma.sync.aligned.m16n8k16.row.col.f32.f16.f16.f32 "
        "{%0,%1,%2,%3},{%4,%5,%6,%7},{%8,%9},{%0,%1,%2,%3};"
        : "+f"(c0), "+f"(c1), "+f"(c2), "+f"(c3)
        : "r"(a0), "r"(a1), "r"(a2), "r"(a3), "r"(b0), "r"(b1));
}
__device__ __forceinline__ void cp16(void* smem, const void* gmem) {
    unsigned s = (unsigned)__cvta_generic_to_shared(smem);
    asm volatile("cp.async.ca.shared.global [%0], [%1], 16;" :: "r"(s), "l"(gmem));
}
__device__ __forceinline__ void cp16cg(void* smem, const void* gmem) {
    unsigned s = (unsigned)__cvta_generic_to_shared(smem);
    asm volatile("cp.async.cg.shared.global [%0], [%1], 16;" :: "r"(s), "l"(gmem));
}
__device__ __forceinline__ void cp_commit() { asm volatile("cp.async.commit_group;"); }
__device__ __forceinline__ void cp_wait1()  { asm volatile("cp.async.wait_group 1;"); }
__device__ __forceinline__ void cp_wait0()  { asm volatile("cp.async.wait_group 0;"); }
__device__ __forceinline__ float sigm(float x) { return 1.0f / (1.0f + __expf(-x)); }

__device__ __forceinline__ unsigned packh2(float a, float b) {
    __half2 h = __floats2half2_rn(a, b);
    return *(unsigned*)&h;
}

// ---------------- k_roundbias: round W into g_Wr (+ bias + tag reset) ----------
__global__ void k_roundbias(const float* __restrict__ src, int n4,
                            const float* __restrict__ bi, const float* __restrict__ bh,
                            int aux) {
    int gid = blockIdx.x * blockDim.x + threadIdx.x;
    if (gid < n4) {
        float4 v = ((const float4*)src)[gid];
        v.x = tfr(v.x); v.y = tfr(v.y); v.z = tfr(v.z); v.w = tfr(v.w);
        ((float4*)g_Wr)[gid] = v;
    } else if (aux) {
        int r = gid - n4;
        if (r < NXG) {
            g_bXG[r] = bi[r] + bh[r];
        } else if (r < NXG + 128) {
            int r2 = r - NXG;
            g_tag[r2 >> 6][r2 & 63][0] = 0u;
        }
    }
}

// ---------------- k_embed: X0T[k][s*16+b] rounded ----------------
__global__ void k_embed(const int* __restrict__ x, const float* __restrict__ lang,
                        const float* __restrict__ emb) {
    __shared__ int toks[BATCH];
    int s = blockIdx.x;
    int tid = threadIdx.x;                      // 256
    if (tid < BATCH) toks[tid] = x[tid * SEQ + s];
    __syncthreads();
    int k = tid * 4;
    float4 v[BATCH];
    if (k < 768) {
        #pragma unroll
        for (int b = 0; b < BATCH; b++)
            v[b] = *(const float4*)(lang + ((size_t)(b * SEQ + s)) * 768 + k);
    } else {
        #pragma unroll
        for (int b = 0; b < BATCH; b++)
            v[b] = *(const float4*)(emb + (size_t)toks[b] * 256 + (k - 768));
    }
    #pragma unroll
    for (int i = 0; i < 4; i++) {
        float* dst = g_X0T + (size_t)(k + i) * MTOT + s * 16;
        #pragma unroll
        for (int bq = 0; bq < 4; bq++) {
            float4 w;
            w.x = tfr(((float*)&v[bq * 4 + 0])[i]);
            w.y = tfr(((float*)&v[bq * 4 + 1])[i]);
            w.z = tfr(((float*)&v[bq * 4 + 2])[i]);
            w.w = tfr(((float*)&v[bq * 4 + 3])[i]);
            *(float4*)(dst + bq * 4) = w;
        }
    }
}

// ---------------- tf32 GEMM ----------------
#define AST 136
#define BST 20
#define GSMEM 58368

__global__ __launch_bounds__(256, 1)
void k_gemm(int asel, int csel, const float* __restrict__ bias_ext,
            int N, int act, int mode, int rnd) {
    extern __shared__ float sg[];
    float* As0 = sg;
    float* As1 = sg + 2176;
    float* Bs0 = sg + 4352;
    float* Bs1 = sg + 9472;

    const float* A = (asel == 0) ? g_X0T : (asel == 1 ? g_YT : g_A1T);
    const float* bias = bias_ext ? bias_ext : g_bXG;

    int m0 = blockIdx.y * 128;
    int n0 = blockIdx.x * 256;
    int tid = threadIdx.x, lane = tid & 31, warp = tid >> 5;
    int wm = (warp >> 2) * 64;
    int wn = (warp & 3) * 64;

    float acc[4][8][4];
    #pragma unroll
    for (int a = 0; a < 4; a++)
        #pragma unroll
        for (int b = 0; b < 8; b++)
            #pragma unroll
            for (int q = 0; q < 4; q++) acc[a][b][q] = 0.f;

    auto load_slice = [&](int kk, int buf) {
        int k0 = kk * 16;
        float* Ad = buf ? As1 : As0;
        float* Bd = buf ? Bs1 : Bs0;
        #pragma unroll
        for (int j = 0; j < 2; j++) {
            int id = tid + j * 256;
            int kr = id >> 5, mc = (id & 31) * 4;
            cp16(&Ad[kr * AST + mc], A + (size_t)(k0 + kr) * MTOT + m0 + mc);
        }
        #pragma unroll
        for (int j = 0; j < 4; j++) {
            int id = tid + j * 256;
            int row = id >> 2, kc = (id & 3) * 4;
            cp16(&Bd[row * BST + kc], g_Wr + (size_t)(n0 + row) * KD + k0 + kc);
        }
        cp_commit();
    };

    load_slice(0, 0);

    #pragma unroll 1
    for (int kk = 0; kk < 64; kk++) {
        int buf = kk & 1;
        if (kk < 63) load_slice(kk + 1, buf ^ 1);
        if (kk < 63) cp_wait1(); else cp_wait0();
        __syncthreads();
        const float* Ab = buf ? As1 : As0;
        const float* Bb = buf ? Bs1 : Bs0;

        #pragma unroll
        for (int kt = 0; kt < 2; kt++) {
            int kc = kt * 8 + (lane & 3);
            unsigned af[4][4];
            #pragma unroll
            for (int mt = 0; mt < 4; mt++) {
                int m = wm + mt * 16 + (lane >> 2);
                af[mt][0] = __float_as_uint(Ab[kc * AST + m]);
                af[mt][1] = __float_as_uint(Ab[kc * AST + m + 8]);
                af[mt][2] = __float_as_uint(Ab[(kc + 4) * AST + m]);
                af[mt][3] = __float_as_uint(Ab[(kc + 4) * AST + m + 8]);
            }
            #pragma unroll
            for (int nt = 0; nt < 8; nt++) {
                int rn = wn + nt * 8 + (lane >> 2);
                unsigned b0 = __float_as_uint(Bb[rn * BST + kc]);
                unsigned b1 = __float_as_uint(Bb[rn * BST + kc + 4]);
                #pragma unroll
                for (int mt = 0; mt < 4; mt++)
                    mma_tf32(acc[mt][nt][0], acc[mt][nt][1], acc[mt][nt][2], acc[mt][nt][3],
                             af[mt][0], af[mt][1], af[mt][2], af[mt][3], b0, b1);
            }
        }
        __syncthreads();
    }

    float* C = (csel == 2) ? g_A1T : (csel == 3 ? g_A2 : g_XG);
    #pragma unroll
    for (int mt = 0; mt < 4; mt++) {
        #pragma unroll
        for (int nt = 0; nt < 8; nt++) {
            int r = m0 + wm + mt * 16 + (lane >> 2);
            int n = n0 + wn + nt * 8 + 2 * (lane & 3);
            float v0 = acc[mt][nt][0] + bias[n];
            float v1 = acc[mt][nt][1] + bias[n + 1];
            float v2 = acc[mt][nt][2] + bias[n];
            float v3 = acc[mt][nt][3] + bias[n + 1];
            if (act) {
                v0 = v0 > 0.f ? v0 : 0.01f * v0;
                v1 = v1 > 0.f ? v1 : 0.01f * v1;
                v2 = v2 > 0.f ? v2 : 0.01f * v2;
                v3 = v3 > 0.f ? v3 : 0.01f * v3;
            }
            if (rnd) { v0 = tfr(v0); v1 = tfr(v1); v2 = tfr(v2); v3 = tfr(v3); }
            if (mode == 1) {
                int s1 = r >> 4, b1v = r & 15;
                int s2 = (r + 8) >> 4, b2v = (r + 8) & 15;
                C[((size_t)s1 * NXG + n) * 16 + b1v]     = v0;
                C[((size_t)s1 * NXG + n + 1) * 16 + b1v] = v1;
                C[((size_t)s2 * NXG + n) * 16 + b2v]     = v2;
                C[((size_t)s2 * NXG + n + 1) * 16 + b2v] = v3;
            } else if (mode == 2) {
                C[(size_t)n * MTOT + r]           = v0;
                C[(size_t)(n + 1) * MTOT + r]     = v1;
                C[(size_t)n * MTOT + r + 8]       = v2;
                C[(size_t)(n + 1) * MTOT + r + 8] = v3;
            } else {
                *(float2*)(C + (size_t)r * N + n)       = make_float2(v0, v1);
                *(float2*)(C + (size_t)(r + 8) * N + n) = make_float2(v2, v3);
            }
        }
    }
}

// ---------------- persistent bidirectional LSTM recurrence (fp16 h) ----------
// 128 CTAs x 256 threads. CTA c: dir = c>>6, units u0 = (c&63)*8.
// Warp w: k-quarter q = w&3 (128 wide), gate-pair gp = w>>2 (gates 2gp, 2gp+1).
// Barrier: per-CTA slot tags (release store / acquire poll), NO shared atomics.
#define HSTR 520    // halves per batch row in smem (512 + 8 pad)

__global__ __launch_bounds__(256, 1)
void k_rec(const float* __restrict__ Whh, const int* __restrict__ lengths) {
    __shared__ __half hsm[BATCH * HSTR];
    __shared__ float part[4][4][BATCH][9];     // [q][gate][b][u pad9]

    int tid = threadIdx.x, lane = tid & 31, w = tid >> 5;
    int dir = blockIdx.x >> 6;
    int u0 = (blockIdx.x & 63) * 8;
    int q = w & 3, gp = w >> 2;

    // persistent fp16 weight fragments: 2 gates x 8 k16-tiles x 2 regs = 32 regs
    unsigned wH[2][8][2];
    #pragma unroll
    for (int gi = 0; gi < 2; gi++) {
        int g = gp * 2 + gi;
        const float* wr = Whh + ((size_t)(dir * 2048 + g * 512 + u0 + (lane >> 2))) * 512;
        #pragma unroll
        for (int kt = 0; kt < 8; kt++) {
            int kb = q * 128 + kt * 16 + (lane & 3) * 2;
            wH[gi][kt][0] = packh2(wr[kb],     wr[kb + 1]);
            wH[gi][kt][1] = packh2(wr[kb + 8], wr[kb + 9]);
        }
    }

    int ub = tid & 15, uj = (tid >> 4) & 7;    // cell-update ownership (tid<128)
    int len = lengths[ub];
    float hreg = 0.f, creg = 0.f;
    unsigned* myslot = &g_tag[dir][blockIdx.x & 63][0];
    const unsigned* pollslot = &g_tag[dir][tid & 63][0];

    #pragma unroll 1
    for (int t = 0; t < SEQ; t++) {
        int s = dir ? (SEQ - 1 - t) : t;

        // xg for this step (independent of h)
        float xgv[4];
        if (tid < 128) {
            #pragma unroll
            for (int g = 0; g < 4; g++)
                xgv[g] = __ldcg(&g_XG[((size_t)s * NXG + dir * 2048 + g * 512 + u0 + uj) * 16 + ub]);
        }

        float acc[2][4];
        #pragma unroll
        for (int gi = 0; gi < 2; gi++)
            #pragma unroll
            for (int c = 0; c < 4; c++) acc[gi][c] = 0.f;

        if (t > 0) {
            // wait for all producers of h(t-1): poll 64 distributed slots
            if (tid < 64) {
                unsigned v;
                do {
                    asm volatile("ld.acquire.gpu.global.u32 %0, [%1];" : "=r"(v) : "l"(pollslot));
                } while (v < (unsigned)t);
            }
            __syncthreads();

            // stage h(t-1) fp16 (16KB) via cp.async.cg (L2-coherent)
            const __half* src = &g_h16[(t + 1) & 1][dir][0][0];
            #pragma unroll
            for (int j = 0; j < 4; j++) {
                int ch = tid + j * 256;            // 0..1023 16B chunks
                int b = ch >> 6, k8 = (ch & 63) * 8;
                cp16cg(&hsm[b * HSTR + k8], src + ch * 8);
            }
            cp_commit();
            cp_wait0();
            __syncthreads();

            // gates += h @ Whh^T  (8 k16-tiles per warp, 2 gates)
            int b0r = lane >> 2;
            #pragma unroll
            for (int kt = 0; kt < 8; kt++) {
                int kb = q * 128 + kt * 16 + (lane & 3) * 2;
                unsigned a0 = *(const unsigned*)&hsm[b0r * HSTR + kb];
                unsigned a1 = *(const unsigned*)&hsm[(b0r + 8) * HSTR + kb];
                unsigned a2 = *(const unsigned*)&hsm[b0r * HSTR + kb + 8];
                unsigned a3 = *(const unsigned*)&hsm[(b0r + 8) * HSTR + kb + 8];
                #pragma unroll
                for (int gi = 0; gi < 2; gi++)
                    mma_f16(acc[gi][0], acc[gi][1], acc[gi][2], acc[gi][3],
                            a0, a1, a2, a3, wH[gi][kt][0], wH[gi][kt][1]);
            }
        }

        // store partials
        #pragma unroll
        for (int gi = 0; gi < 2; gi++) {
            int g = gp * 2 + gi;
            part[q][g][lane >> 2][2 * (lane & 3)]           = acc[gi][0];
            part[q][g][lane >> 2][2 * (lane & 3) + 1]       = acc[gi][1];
            part[q][g][(lane >> 2) + 8][2 * (lane & 3)]     = acc[gi][2];
            part[q][g][(lane >> 2) + 8][2 * (lane & 3) + 1] = acc[gi][3];
        }
        __syncthreads();

        // cell update (tid < 128)
        if (tid < 128) {
            float v[4];
            #pragma unroll
            for (int g = 0; g < 4; g++)
                v[g] = part[0][g][ub][uj] + part[1][g][ub][uj]
                     + part[2][g][ub][uj] + part[3][g][ub][uj] + xgv[g];
            float gi = sigm(v[0]);
            float gf = sigm(v[1]);
            float gg = tanhf(v[2]);
            float go = sigm(v[3]);
            float cn = gf * creg + gi * gg;
            float hn = go * tanhf(cn);
            bool active = s < len;
            float y = active ? hn : 0.f;
            if (active) { creg = cn; hreg = hn; }

            g_YT[(size_t)(dir * 512 + u0 + uj) * MTOT + s * 16 + ub] = tfr(y);
            unsigned short hb = __half_as_ushort(__float2half_rn(hreg));
            asm volatile("st.global.cg.u16 [%0], %1;"
                         :: "l"(&g_h16[t & 1][dir][ub][u0 + uj]), "h"(hb));
        }
        __syncthreads();

        // publish h(t): release-store step tag to own slot
        if (tid == 0) {
            asm volatile("st.release.gpu.global.u32 [%0], %1;"
                         :: "l"(myslot), "r"((unsigned)(t + 1)));
        }
    }
}

// ---------------- head ----------------
__global__ void k_head(const float* __restrict__ W3, const float* __restrict__ b3,
                       float* __restrict__ out) {
    int gw = (blockIdx.x * blockDim.x + threadIdx.x) >> 5;
    int lane = threadIdx.x & 31;
    if (gw >= MTOT) return;
    const float* a = g_A2 + (size_t)gw * KD;
    float s0 = 0, s1 = 0, s2 = 0, s3 = 0, s4 = 0;
    for (int k = lane; k < KD; k += 32) {
        float v = a[k];
        s0 += v * W3[k];
        s1 += v * W3[1024 + k];
        s2 += v * W3[2048 + k];
        s3 += v * W3[3072 + k];
        s4 += v * W3[4096 + k];
    }
    #pragma unroll
    for (int o = 16; o; o >>= 1) {
        s0 += __shfl_down_sync(0xffffffffu, s0, o);
        s1 += __shfl_down_sync(0xffffffffu, s1, o);
        s2 += __shfl_down_sync(0xffffffffu, s2, o);
        s3 += __shfl_down_sync(0xffffffffu, s3, o);
        s4 += __shfl_down_sync(0xffffffffu, s4, o);
    }
    if (lane == 0) {
        int b = gw & 15, s = gw >> 4;
        float* o = out + ((size_t)b * SEQ + s) * 5;
        o[0] = s0 + b3[0];
        o[1] = s1 + b3[1];
        o[2] = s2 + b3[2];
        o[3] = s3 + b3[3];
        o[4] = s4 + b3[4];
    }
}

// ---------------- launch ----------------
extern "C" void kernel_launch(void* const* d_in, const int* in_sizes, int n_in,
                              void* d_out, int out_size) {
    const int*   x    = (const int*)d_in[0];
    const int*   len  = (const int*)d_in[1];
    const float* lang = (const float*)d_in[2];
    const float* emb  = (const float*)d_in[3];
    const float* W_ih = (const float*)d_in[4];
    const float* W_hh = (const float*)d_in[5];
    const float* b_ih = (const float*)d_in[6];
    const float* b_hh = (const float*)d_in[7];
    const float* W1   = (const float*)d_in[8];
    const float* b1   = (const float*)d_in[9];
    const float* W2   = (const float*)d_in[10];
    const float* b2   = (const float*)d_in[11];
    const float* W3   = (const float*)d_in[12];
    const float* b3   = (const float*)d_in[13];
    float* out = (float*)d_out;

    cudaFuncSetAttribute(k_gemm, cudaFuncAttributeMaxDynamicSharedMemorySize, GSMEM);

    k_embed<<<SEQ, 256>>>(x, lang, emb);

    for (int l = 0; l < 2; l++) {
        // round W_ih[l] + bias + tag reset (aux=1)
        k_roundbias<<<4113, 256>>>(W_ih + (size_t)l * NXG * KD, NXG * KD / 4,
                                   b_ih + (size_t)l * NXG, b_hh + (size_t)l * NXG, 1);
        k_gemm<<<dim3(NXG / 256, MTOT / 128), 256, GSMEM>>>(
            l == 0 ? 0 : 1, 4, nullptr, NXG, 0, 1, 0);
        k_rec<<<128, 256>>>(W_hh + (size_t)l * 2 * 2048 * 512, len);
    }

    k_roundbias<<<1024, 256>>>(W1, KD * KD / 4, nullptr, nullptr, 0);
    k_gemm<<<dim3(KD / 256, MTOT / 128), 256, GSMEM>>>(1, 2, b1, KD, 1, 2, 1);
    k_roundbias<<<1024, 256>>>(W2, KD * KD / 4, nullptr, nullptr, 0);
    k_gemm<<<dim3(KD / 256, MTOT / 128), 256, GSMEM>>>(2, 3, b2, KD, 1, 0, 0);
    k_head<<<MTOT / 8, 256>>>(W3, b3, out);
}